// round 6
// baseline (speedup 1.0000x reference)
#include <cuda_runtime.h>
#include <cuda_bf16.h>

// Shape fixed by dataset: disp [4,1,1024,1280] f32, kernel_raw [4,8,1024,1280] f32
#define BB    4
#define HH    1024
#define WW    1280
#define PLANE (HH * WW)
#define NPIX  (BB * PLANE)     // 5242880
#define NITER 24

#define TT    4                // fused iterations per pass
#define TS    56               // output tile
#define RS    64               // region tile (halo 4 each side)
#define NTX   ((WW + TS - 1) / TS)   // 23
#define NTY   ((HH + TS - 1) / TS)   // 19
#define FULLMASK 0xFFFFFFFFu

__device__ float g_w[(size_t)8 * NPIX];   // normalized weights, planar [8][B*H*W]
__device__ float g_ping[NPIX];            // ping-pong disparity buffer

// ---------------------------------------------------------------------------
// Fused pass: 4 stencil iterations. Thread layout: warp = 32 consecutive rows
// of one 8-px column octet (lane = row-in-warp). Own row lives in registers;
// vertical neighbors via shfl; lateral halo (2 floats) + warp-boundary rows
// (rows 31/32) via tiny smem buffers, parity double-buffered, 1 sync/iter.
// PREP: pass 1 normalizes kernel_raw in-register and stores g_w for its
// owned window (overlap-free tiling of the image).
// ---------------------------------------------------------------------------
template <bool PREP, bool CLIP>
__global__ void __launch_bounds__(512) fused_kernel(const float* __restrict__ din,
                                                    float* __restrict__ dout,
                                                    const float* __restrict__ raw) {
    __shared__ float haloL[2][8][64];   // [parity][octet][row] = mm[1] (px x0)
    __shared__ float haloR[2][8][64];   // [parity][octet][row] = mm[8] (px x0+7)
    __shared__ float rowT[2][8][8];     // row 31's mm[1..8]
    __shared__ float rowB[2][8][8];     // row 32's mm[1..8]

    const int tid  = threadIdx.x;
    const int lane = tid & 31;
    const int wid  = tid >> 5;
    const int c    = wid >> 1;          // octet 0..7
    const int v    = wid & 1;           // vertical half
    const int r    = v * 32 + lane;     // region row 0..63

    const int b   = blockIdx.z;
    const int gy  = blockIdx.y * TS - TT + r;
    const int gxb = blockIdx.x * TS - TT + (c << 3);
    const bool rowIn = (gy >= 0) && (gy < HH);
    const size_t rowOff = (size_t)(b * HH + gy) * WW;   // deref'd only when rowIn

    // ---- load own disparity row (px -1 .. 8), zero outside image ----
    float mm[10];
#pragma unroll
    for (int k = 0; k < 2; k++) {
        int gx = gxb + 4 * k;
        float4 q = make_float4(0.f, 0.f, 0.f, 0.f);
        if (rowIn && gx >= 0 && gx < WW)
            q = *reinterpret_cast<const float4*>(din + rowOff + gx);
        mm[1 + 4 * k] = q.x; mm[2 + 4 * k] = q.y;
        mm[3 + 4 * k] = q.z; mm[4 + 4 * k] = q.w;
    }
    // strict both-sided guards (gxb can exceed WW on the right-edge octet!)
    mm[0] = (rowIn && gxb >= 1 && gxb < WW)         ? din[rowOff + gxb - 1] : 0.f;
    mm[9] = (rowIn && gxb + 8 >= 0 && gxb + 8 < WW) ? din[rowOff + gxb + 8] : 0.f;

    // ---- per-pixel weights into registers (zero outside image) ----
    float w[8][8];                      // [channel][px]
#pragma unroll
    for (int ch = 0; ch < 8; ch++) {
        const float* base = PREP
            ? raw + (size_t)(b * 8 + ch) * PLANE
            : g_w + (size_t)ch * NPIX + (size_t)b * PLANE;
#pragma unroll
        for (int k = 0; k < 2; k++) {
            int gx = gxb + 4 * k;
            float4 q = make_float4(0.f, 0.f, 0.f, 0.f);
            if (rowIn && gx >= 0 && gx < WW)
                q = *reinterpret_cast<const float4*>(base + (size_t)gy * WW + gx);
            w[ch][4 * k + 0] = q.x; w[ch][4 * k + 1] = q.y;
            w[ch][4 * k + 2] = q.z; w[ch][4 * k + 3] = q.w;
        }
    }

    if (PREP) {
        // normalize: w[ch] /= (sum_ch |w| + 1e-9)
#pragma unroll
        for (int p = 0; p < 8; p++) {
            float s = 0.f;
#pragma unroll
            for (int ch = 0; ch < 8; ch++) s += fabsf(w[ch][p]);
            float inv = __frcp_rn(s + 1e-9f);
#pragma unroll
            for (int ch = 0; ch < 8; ch++) w[ch][p] *= inv;
        }
        // store owned window to g_w (non-overlapping tiling of the image)
        if (r >= TT && r < RS - TT && gy < HH) {
#pragma unroll
            for (int ch = 0; ch < 8; ch++) {
                float* wbase = g_w + (size_t)ch * NPIX + rowOff;
                if (c != 0 && gxb < WW)
                    *reinterpret_cast<float4*>(wbase + gxb) =
                        make_float4(w[ch][0], w[ch][1], w[ch][2], w[ch][3]);
                if (c != 7 && gxb + 4 < WW)
                    *reinterpret_cast<float4*>(wbase + gxb + 4) =
                        make_float4(w[ch][4], w[ch][5], w[ch][6], w[ch][7]);
            }
        }
    }

    float w0[8];
#pragma unroll
    for (int p = 0; p < 8; p++) {
        float s = ((w[0][p] + w[1][p]) + (w[2][p] + w[3][p])) +
                  ((w[4][p] + w[5][p]) + (w[6][p] + w[7][p]));
        w0[p] = 1.0f - s;
    }

    const bool topBuf = (v == 1) && (lane == 0);    // row 32: top row via smem
    const bool botBuf = (v == 0) && (lane == 31);   // row 31: bottom row via smem
    const bool act    = (r >= 1) && (r <= RS - 2);

    // ---- 4 fused iterations ----
#pragma unroll
    for (int it = 0; it < TT; it++) {
        const int par = it & 1;
        // publish lateral halo + warp-boundary rows (current state)
        haloL[par][c][r] = mm[1];
        haloR[par][c][r] = mm[8];
        if (botBuf) {
#pragma unroll
            for (int i = 0; i < 8; i++) rowT[par][c][i] = mm[1 + i];
        }
        if (topBuf) {
#pragma unroll
            for (int i = 0; i < 8; i++) rowB[par][c][i] = mm[1 + i];
        }
        __syncthreads();

        // refresh lateral halo (uniform per warp)
        if (c > 0) mm[0] = haloR[par][c - 1][r];
        if (c < 7) mm[9] = haloL[par][c + 1][r];

        // mid-row terms (all register-resident)
        float acc[8];
#pragma unroll
        for (int p = 0; p < 8; p++) {
            float a = w0[p] * mm[p + 1];
            a = fmaf(w[3][p], mm[p + 2], a);   // (y, x+1)
            a = fmaf(w[7][p], mm[p],     a);   // (y, x-1)
            acc[p] = a;
        }

        // vertical terms via shuffle (cross-warp rows via smem buffers)
#pragma unroll
        for (int i = 0; i < 10; i++) {
            float t  = __shfl_up_sync(FULLMASK, mm[i], 1);    // row r-1
            float bt = __shfl_down_sync(FULLMASK, mm[i], 1);  // row r+1
            if (topBuf) {
                if (i == 0)      t = (c > 0) ? haloR[par][c - 1][31] : 0.f;
                else if (i == 9) t = (c < 7) ? haloL[par][c + 1][31] : 0.f;
                else             t = rowT[par][c][i - 1];
            }
            if (botBuf) {
                if (i == 0)      bt = (c > 0) ? haloR[par][c - 1][32] : 0.f;
                else if (i == 9) bt = (c < 7) ? haloL[par][c + 1][32] : 0.f;
                else             bt = rowB[par][c][i - 1];
            }
            if (i < 8) {
                acc[i] = fmaf(w[0][i], t,  acc[i]);   // (y-1, x-1)
                acc[i] = fmaf(w[6][i], bt, acc[i]);   // (y+1, x-1)
            }
            if (i >= 1 && i <= 8) {
                acc[i - 1] = fmaf(w[1][i - 1], t,  acc[i - 1]);  // (y-1, x)
                acc[i - 1] = fmaf(w[5][i - 1], bt, acc[i - 1]);  // (y+1, x)
            }
            if (i >= 2) {
                acc[i - 2] = fmaf(w[2][i - 2], t,  acc[i - 2]);  // (y-1, x+1)
                acc[i - 2] = fmaf(w[4][i - 2], bt, acc[i - 2]);  // (y+1, x+1)
            }
        }

        // region-edge fixups + state update (inactive rows keep old values)
        if (act) {
            if (c == 0) acc[0] = mm[1];
            if (c == 7) acc[7] = mm[8];
#pragma unroll
            for (int p = 0; p < 8; p++) mm[1 + p] = acc[p];
        }
    }

    // ---- epilogue: write owned window ----
    if (r >= TT && r < RS - TT && gy < HH) {
        if (CLIP) {
#pragma unroll
            for (int p = 0; p < 8; p++)
                mm[1 + p] = fminf(fmaxf(mm[1 + p], 0.f), 256.f);
        }
        if (c != 0 && gxb < WW)
            *reinterpret_cast<float4*>(dout + rowOff + gxb) =
                make_float4(mm[1], mm[2], mm[3], mm[4]);
        if (c != 7 && gxb + 4 < WW)
            *reinterpret_cast<float4*>(dout + rowOff + gxb + 4) =
                make_float4(mm[5], mm[6], mm[7], mm[8]);
    }
}

// ---------------------------------------------------------------------------
extern "C" void kernel_launch(void* const* d_in, const int* in_sizes, int n_in,
                              void* d_out, int out_size) {
    const float* disp = (const float*)d_in[0];
    const float* raw  = (const float*)d_in[1];
    if (n_in >= 2 && in_sizes[0] > in_sizes[1]) {  // defensive order check
        const float* t = disp; disp = raw; raw = t;
    }
    float* out = (float*)d_out;

    float* ping = nullptr;
    cudaGetSymbolAddress((void**)&ping, g_ping);   // address query; capture-safe

    dim3 grid(NTX, NTY, BB);
    // 6 fused passes x 4 iterations = 24; pass 1 also normalizes weights
    fused_kernel<true,  false><<<grid, 512>>>(disp, ping, raw);
    fused_kernel<false, false><<<grid, 512>>>(ping, out,  raw);
    fused_kernel<false, false><<<grid, 512>>>(out,  ping, raw);
    fused_kernel<false, false><<<grid, 512>>>(ping, out,  raw);
    fused_kernel<false, false><<<grid, 512>>>(out,  ping, raw);
    fused_kernel<false, true ><<<grid, 512>>>(ping, out,  raw);
}

// round 7
// speedup vs baseline: 1.6193x; 1.6193x over previous
#include <cuda_runtime.h>
#include <cuda_bf16.h>

// Shape fixed by dataset: disp [4,1,1024,1280] f32, kernel_raw [4,8,1024,1280] f32
#define BB    4
#define HH    1024
#define WW    1280
#define PLANE (HH * WW)
#define NPIX  (BB * PLANE)     // 5242880
#define NITER 24

#define TT    4                // fused iterations per pass
#define TS    56               // output tile
#define RS    64               // region tile (halo 4 each side)
#define NTX   ((WW + TS - 1) / TS)   // 23
#define NTY   ((HH + TS - 1) / TS)   // 19

__device__ float g_w[(size_t)8 * NPIX];   // normalized weights, planar [8][B*H*W]
__device__ float g_ping[NPIX];            // ping-pong disparity buffer

// Quad-interleaved row layout: row of 64 px stored as 16 16-byte slots,
// slot(j,c) = j*8 + c  (c = octet 0..7, j = quad 0..1 within octet).
// phys float idx for px x: o=x>>3, j=(x>>2)&1, p=x&3 -> j*32 + o*4 + p.
// Quarter-warp (same r, c=0..7) wide accesses hit banks 4c..4c+3: conflict-free.
#define SROW 64                 // floats per smem row

// ---------------------------------------------------------------------------
// Fused pass: 4 stencil iterations, trapezoidal blocking (64x64 region ->
// 56x56 output). Thread map as round 2: r = tid>>3 (region row), c = tid&7
// (8-px octet) — warp covers 4 rows, global loads line-coalesced.
// Mid row lives in registers; top/bottom rows read from conflict-free smem.
// Update form: d' = d + sum_i w_i * (d_i - d)   (no center weight needed).
// PREP: pass 1 normalizes kernel_raw in-register and stores g_w for its
// owned (non-overlapping) window.
// ---------------------------------------------------------------------------
template <bool PREP, bool CLIP>
__global__ void __launch_bounds__(512) fused_kernel(const float* __restrict__ din,
                                                    float* __restrict__ dout,
                                                    const float* __restrict__ raw) {
    __shared__ float sbuf[2][RS * SROW];

    const int tid = threadIdx.x;
    const int c   = tid & 7;            // octet
    const int r   = tid >> 3;           // region row 0..63

    const int b   = blockIdx.z;
    const int gy  = blockIdx.y * TS - TT + r;
    const int gx0 = blockIdx.x * TS - TT + (c << 3);   // global col of px0 (mult of 4)
    const bool rowIn = (gy >= 0) && (gy < HH);
    const size_t rowOff = (size_t)(b * HH + gy) * WW;  // deref'd only when rowIn

    // smem slot indices for this thread's octet
    const int q0Idx = c * 4;                    // quad0 (px 8c..8c+3)
    const int q1Idx = 32 + c * 4;               // quad1 (px 8c+4..8c+7)
    const int hlIdx = 32 + ((c + 7) & 7) * 4 + 3;  // px (8c-1)&63
    const int hrIdx = ((c + 1) & 7) * 4;           // px (8c+8)&63

    // ---- own disparity row px0..px7 (zero outside image) ----
    float mm[10];                        // [halo-1, px0..7, halo+8]
#pragma unroll
    for (int k = 0; k < 2; k++) {
        int gx = gx0 + 4 * k;
        float4 q = make_float4(0.f, 0.f, 0.f, 0.f);
        if (rowIn && gx >= 0 && gx < WW)
            q = *reinterpret_cast<const float4*>(din + rowOff + gx);
        mm[1 + 4 * k] = q.x; mm[2 + 4 * k] = q.y;
        mm[3 + 4 * k] = q.z; mm[4 + 4 * k] = q.w;
    }

    // ---- per-pixel weights into registers (zero outside image) ----
    float w[8][8];                       // [channel][px]
#pragma unroll
    for (int ch = 0; ch < 8; ch++) {
        const float* base = PREP
            ? raw + (size_t)(b * 8 + ch) * PLANE
            : g_w + (size_t)ch * NPIX + (size_t)b * PLANE;
#pragma unroll
        for (int k = 0; k < 2; k++) {
            int gx = gx0 + 4 * k;
            float4 q = make_float4(0.f, 0.f, 0.f, 0.f);
            if (rowIn && gx >= 0 && gx < WW)
                q = *reinterpret_cast<const float4*>(base + (size_t)gy * WW + gx);
            w[ch][4 * k + 0] = q.x; w[ch][4 * k + 1] = q.y;
            w[ch][4 * k + 2] = q.z; w[ch][4 * k + 3] = q.w;
        }
    }

    if (PREP) {
#pragma unroll
        for (int p = 0; p < 8; p++) {
            float s = 0.f;
#pragma unroll
            for (int ch = 0; ch < 8; ch++) s += fabsf(w[ch][p]);
            float inv = __frcp_rn(s + 1e-9f);
#pragma unroll
            for (int ch = 0; ch < 8; ch++) w[ch][p] *= inv;
        }
        // store owned (non-overlapping) window to g_w
        if (r >= TT && r < RS - TT && gy < HH) {
#pragma unroll
            for (int ch = 0; ch < 8; ch++) {
                float* wbase = g_w + (size_t)ch * NPIX + rowOff;
                if (c != 0 && gx0 < WW)
                    *reinterpret_cast<float4*>(wbase + gx0) =
                        make_float4(w[ch][0], w[ch][1], w[ch][2], w[ch][3]);
                if (c != 7 && gx0 + 4 < WW)
                    *reinterpret_cast<float4*>(wbase + gx0 + 4) =
                        make_float4(w[ch][4], w[ch][5], w[ch][6], w[ch][7]);
            }
        }
    }

    // ---- initial publish to buffer 0 ----
    {
        float* row = &sbuf[0][r * SROW];
        *reinterpret_cast<float4*>(row + q0Idx) = make_float4(mm[1], mm[2], mm[3], mm[4]);
        *reinterpret_cast<float4*>(row + q1Idx) = make_float4(mm[5], mm[6], mm[7], mm[8]);
    }
    __syncthreads();

    const bool act = (r >= 1) && (r <= RS - 2);
    const int  tr  = (r >= 1) ? r - 1 : 0;        // clamped (inactive rows: result unused)
    const int  br  = (r <= RS - 2) ? r + 1 : RS - 1;

    // ---- 4 fused iterations ----
#pragma unroll
    for (int it = 0; it < TT; it++) {
        const float* cur = sbuf[it & 1];

        float tm[10], bm[10];
        {
            const float* trow = cur + tr * SROW;
            float4 a = *reinterpret_cast<const float4*>(trow + q0Idx);
            float4 d = *reinterpret_cast<const float4*>(trow + q1Idx);
            tm[1]=a.x; tm[2]=a.y; tm[3]=a.z; tm[4]=a.w;
            tm[5]=d.x; tm[6]=d.y; tm[7]=d.z; tm[8]=d.w;
            tm[0]=trow[hlIdx]; tm[9]=trow[hrIdx];
        }
        {
            const float* brow = cur + br * SROW;
            float4 a = *reinterpret_cast<const float4*>(brow + q0Idx);
            float4 d = *reinterpret_cast<const float4*>(brow + q1Idx);
            bm[1]=a.x; bm[2]=a.y; bm[3]=a.z; bm[4]=a.w;
            bm[5]=d.x; bm[6]=d.y; bm[7]=d.z; bm[8]=d.w;
            bm[0]=brow[hlIdx]; bm[9]=brow[hrIdx];
        }
        {
            const float* mrow = cur + r * SROW;
            mm[0] = mrow[hlIdx];
            mm[9] = mrow[hrIdx];
        }

        float acc[8];
#pragma unroll
        for (int p = 0; p < 8; p++) {
            float d = mm[p + 1];
            float a = d;
            a = fmaf(w[0][p], tm[p]     - d, a);  // (y-1, x-1)
            a = fmaf(w[1][p], tm[p + 1] - d, a);  // (y-1, x  )
            a = fmaf(w[2][p], tm[p + 2] - d, a);  // (y-1, x+1)
            a = fmaf(w[3][p], mm[p + 2] - d, a);  // (y  , x+1)
            a = fmaf(w[4][p], bm[p + 2] - d, a);  // (y+1, x+1)
            a = fmaf(w[5][p], bm[p + 1] - d, a);  // (y+1, x  )
            a = fmaf(w[6][p], bm[p]     - d, a);  // (y+1, x-1)
            a = fmaf(w[7][p], mm[p]     - d, a);  // (y  , x-1)
            acc[p] = a;
        }
        // region-edge columns keep old value (trapezoid: consumed only while valid)
        if (c == 0) acc[0] = mm[1];
        if (c == 7) acc[7] = mm[8];

        if (act) {
#pragma unroll
            for (int p = 0; p < 8; p++) mm[1 + p] = acc[p];
        }

        if (it < TT - 1) {
            float* nrow = &sbuf[(it + 1) & 1][r * SROW];
            *reinterpret_cast<float4*>(nrow + q0Idx) = make_float4(mm[1], mm[2], mm[3], mm[4]);
            *reinterpret_cast<float4*>(nrow + q1Idx) = make_float4(mm[5], mm[6], mm[7], mm[8]);
            __syncthreads();
        }
    }

    // ---- epilogue: write owned window ----
    if (r >= TT && r < RS - TT && gy < HH) {
        if (CLIP) {
#pragma unroll
            for (int p = 0; p < 8; p++)
                mm[1 + p] = fminf(fmaxf(mm[1 + p], 0.f), 256.f);
        }
        if (c != 0 && gx0 < WW)
            *reinterpret_cast<float4*>(dout + rowOff + gx0) =
                make_float4(mm[1], mm[2], mm[3], mm[4]);
        if (c != 7 && gx0 + 4 < WW)
            *reinterpret_cast<float4*>(dout + rowOff + gx0 + 4) =
                make_float4(mm[5], mm[6], mm[7], mm[8]);
    }
}

// ---------------------------------------------------------------------------
extern "C" void kernel_launch(void* const* d_in, const int* in_sizes, int n_in,
                              void* d_out, int out_size) {
    const float* disp = (const float*)d_in[0];
    const float* raw  = (const float*)d_in[1];
    if (n_in >= 2 && in_sizes[0] > in_sizes[1]) {  // defensive order check
        const float* t = disp; disp = raw; raw = t;
    }
    float* out = (float*)d_out;

    float* ping = nullptr;
    cudaGetSymbolAddress((void**)&ping, g_ping);   // address query; capture-safe

    dim3 grid(NTX, NTY, BB);
    // 6 fused passes x 4 iterations = 24; pass 1 also normalizes weights
    fused_kernel<true,  false><<<grid, 512>>>(disp, ping, raw);
    fused_kernel<false, false><<<grid, 512>>>(ping, out,  raw);
    fused_kernel<false, false><<<grid, 512>>>(out,  ping, raw);
    fused_kernel<false, false><<<grid, 512>>>(ping, out,  raw);
    fused_kernel<false, false><<<grid, 512>>>(out,  ping, raw);
    fused_kernel<false, true ><<<grid, 512>>>(ping, out,  raw);
}

// round 9
// speedup vs baseline: 1.8483x; 1.1414x over previous
#include <cuda_runtime.h>
#include <cuda_bf16.h>

// Shape fixed by dataset: disp [4,1,1024,1280] f32, kernel_raw [4,8,1024,1280] f32
#define BB    4
#define HH    1024
#define WW    1280
#define PLANE (HH * WW)
#define NPIX  (BB * PLANE)     // 5242880
#define NITER 24

#define TT    4                // fused iterations per pass
#define TS    56               // output tile
#define RS    64               // region tile (halo 4 each side)
#define NTX   ((WW + TS - 1) / TS)   // 23
#define NTY   ((HH + TS - 1) / TS)   // 19
#define SROW  64               // floats per smem row (linear layout)

__device__ float g_w[(size_t)8 * NPIX];   // normalized weights, planar [8][B*H*W]
__device__ float g_ping[NPIX];            // ping-pong disparity buffer

// ---------------------------------------------------------------------------
// Fused pass: 4 stencil iterations, trapezoidal blocking (64x64 region ->
// 56x56 output). 1024 threads/CTA, 4 px/thread (one float4 quad):
//   q = tid & 15 (quad 0..15), r = tid >> 4 (region row 0..63).
// Weights in registers (32), own quad in registers, neighbor rows from
// conflict-free smem (wide loads phase-split; only scalar halos 4-way).
// Update form: d' = d + sum_i w_i * (d_i - d).
// PREP: pass 1 normalizes kernel_raw in-register and stores g_w for its
// owned (non-overlapping) window.
// ---------------------------------------------------------------------------
template <bool PREP, bool CLIP>
__global__ void __launch_bounds__(1024) fused_kernel(const float* __restrict__ din,
                                                     float* __restrict__ dout,
                                                     const float* __restrict__ raw) {
    __shared__ float sbuf[2][RS * SROW];

    const int tid = threadIdx.x;
    const int q   = tid & 15;           // quad
    const int r   = tid >> 4;           // region row 0..63
    const int x0  = q << 2;             // region col of px0

    const int b   = blockIdx.z;
    const int gy  = blockIdx.y * TS - TT + r;
    const int gx0 = blockIdx.x * TS - TT + x0;         // global col of px0
    const bool rowIn = (gy >= 0) && (gy < HH);
    const size_t rowOff = (size_t)(b * HH + gy) * WW;  // deref'd only when rowIn

    const int hlIdx = (x0 - 1) & 63;    // left halo px (wraps for q=0: unused)
    const int hrIdx = (x0 + 4) & 63;    // right halo px (wraps for q=15: unused)

    // ---- own disparity quad (zero outside image) ----
    float mm[6];                         // [halo-1, px0..3, halo+4]
    {
        float4 v = make_float4(0.f, 0.f, 0.f, 0.f);
        if (rowIn && gx0 >= 0 && gx0 < WW)
            v = *reinterpret_cast<const float4*>(din + rowOff + gx0);
        mm[1] = v.x; mm[2] = v.y; mm[3] = v.z; mm[4] = v.w;
    }

    // ---- per-pixel weights into registers (zero outside image) ----
    float w[8][4];                       // [channel][px]
#pragma unroll
    for (int ch = 0; ch < 8; ch++) {
        const float* base = PREP
            ? raw + (size_t)(b * 8 + ch) * PLANE
            : g_w + (size_t)ch * NPIX + (size_t)b * PLANE;
        float4 v = make_float4(0.f, 0.f, 0.f, 0.f);
        if (rowIn && gx0 >= 0 && gx0 < WW)
            v = *reinterpret_cast<const float4*>(base + (size_t)gy * WW + gx0);
        w[ch][0] = v.x; w[ch][1] = v.y; w[ch][2] = v.z; w[ch][3] = v.w;
    }

    if (PREP) {
#pragma unroll
        for (int p = 0; p < 4; p++) {
            float s = 0.f;
#pragma unroll
            for (int ch = 0; ch < 8; ch++) s += fabsf(w[ch][p]);
            float inv = __frcp_rn(s + 1e-9f);
#pragma unroll
            for (int ch = 0; ch < 8; ch++) w[ch][p] *= inv;
        }
        // store owned (non-overlapping) window: region cols [4,60), rows [4,60)
        if (q >= 1 && q <= 14 && r >= TT && r < RS - TT && gy < HH && gx0 < WW) {
#pragma unroll
            for (int ch = 0; ch < 8; ch++)
                *reinterpret_cast<float4*>(g_w + (size_t)ch * NPIX + rowOff + gx0) =
                    make_float4(w[ch][0], w[ch][1], w[ch][2], w[ch][3]);
        }
    }

    // ---- initial publish to buffer 0 ----
    *reinterpret_cast<float4*>(&sbuf[0][r * SROW + x0]) =
        make_float4(mm[1], mm[2], mm[3], mm[4]);
    __syncthreads();

    const bool act = (r >= 1) && (r <= RS - 2);
    const int  tr  = (r >= 1) ? r - 1 : 0;          // clamped (result unused when inactive)
    const int  br  = (r <= RS - 2) ? r + 1 : RS - 1;

    // ---- 4 fused iterations ----
#pragma unroll
    for (int it = 0; it < TT; it++) {
        const float* cur = sbuf[it & 1];

        // mid-row halos
        mm[0] = cur[r * SROW + hlIdx];
        mm[5] = cur[r * SROW + hrIdx];

        float t[6], acc[4];

        // top row terms
        {
            const float* trow = cur + tr * SROW;
            float4 a = *reinterpret_cast<const float4*>(trow + x0);
            t[1] = a.x; t[2] = a.y; t[3] = a.z; t[4] = a.w;
            t[0] = trow[hlIdx]; t[5] = trow[hrIdx];
        }
#pragma unroll
        for (int p = 0; p < 4; p++) {
            float d = mm[p + 1];
            float a = d;
            a = fmaf(w[0][p], t[p]      - d, a);  // (y-1, x-1)
            a = fmaf(w[1][p], t[p + 1]  - d, a);  // (y-1, x  )
            a = fmaf(w[2][p], t[p + 2]  - d, a);  // (y-1, x+1)
            a = fmaf(w[3][p], mm[p + 2] - d, a);  // (y  , x+1)
            a = fmaf(w[7][p], mm[p]     - d, a);  // (y  , x-1)
            acc[p] = a;
        }

        // bottom row terms (reuse t[])
        {
            const float* brow = cur + br * SROW;
            float4 a = *reinterpret_cast<const float4*>(brow + x0);
            t[1] = a.x; t[2] = a.y; t[3] = a.z; t[4] = a.w;
            t[0] = brow[hlIdx]; t[5] = brow[hrIdx];
        }
#pragma unroll
        for (int p = 0; p < 4; p++) {
            float d = mm[p + 1];
            acc[p] = fmaf(w[4][p], t[p + 2] - d, acc[p]);  // (y+1, x+1)
            acc[p] = fmaf(w[5][p], t[p + 1] - d, acc[p]);  // (y+1, x  )
            acc[p] = fmaf(w[6][p], t[p]     - d, acc[p]);  // (y+1, x-1)
        }

        // region-edge columns keep old value (consumed only while still valid)
        if (q == 0)  acc[0] = mm[1];
        if (q == 15) acc[3] = mm[4];

        if (act) {
            mm[1] = acc[0]; mm[2] = acc[1]; mm[3] = acc[2]; mm[4] = acc[3];
        }

        if (it < TT - 1) {
            *reinterpret_cast<float4*>(&sbuf[(it + 1) & 1][r * SROW + x0]) =
                make_float4(mm[1], mm[2], mm[3], mm[4]);
            __syncthreads();
        }
    }

    // ---- epilogue: write owned window (region cols [4,60), rows [4,60)) ----
    if (q >= 1 && q <= 14 && r >= TT && r < RS - TT && gy < HH && gx0 < WW) {
        if (CLIP) {
#pragma unroll
            for (int p = 0; p < 4; p++)
                mm[1 + p] = fminf(fmaxf(mm[1 + p], 0.f), 256.f);
        }
        *reinterpret_cast<float4*>(dout + rowOff + gx0) =
            make_float4(mm[1], mm[2], mm[3], mm[4]);
    }
}

// ---------------------------------------------------------------------------
extern "C" void kernel_launch(void* const* d_in, const int* in_sizes, int n_in,
                              void* d_out, int out_size) {
    const float* disp = (const float*)d_in[0];
    const float* raw  = (const float*)d_in[1];
    if (n_in >= 2 && in_sizes[0] > in_sizes[1]) {  // defensive order check
        const float* t = disp; disp = raw; raw = t;
    }
    float* out = (float*)d_out;

    float* ping = nullptr;
    cudaGetSymbolAddress((void**)&ping, g_ping);   // address query; capture-safe

    dim3 grid(NTX, NTY, BB);
    // 6 fused passes x 4 iterations = 24; pass 1 also normalizes weights
    fused_kernel<true,  false><<<grid, 1024>>>(disp, ping, raw);
    fused_kernel<false, false><<<grid, 1024>>>(ping, out,  raw);
    fused_kernel<false, false><<<grid, 1024>>>(out,  ping, raw);
    fused_kernel<false, false><<<grid, 1024>>>(ping, out,  raw);
    fused_kernel<false, false><<<grid, 1024>>>(out,  ping, raw);
    fused_kernel<false, true ><<<grid, 1024>>>(ping, out,  raw);
}

// round 12
// speedup vs baseline: 2.1524x; 1.1646x over previous
#include <cuda_runtime.h>

// Shape fixed by dataset: disp [4,1,1024,1280] f32, kernel_raw [4,8,1024,1280] f32
#define BB    4
#define HH    1024
#define WW    1280
#define PLANE (HH * WW)
#define NPIX  (BB * PLANE)     // 5242880

#define TT    8                // fused iterations per pass (24 = 3 passes)
#define TS    48               // output tile (quad-aligned: halo 8 = 2 quads)
#define RS    64               // region tile
#define NTX   ((WW + TS - 1) / TS)   // 27
#define NTY   ((HH + TS - 1) / TS)   // 22
#define SROW  64               // floats per smem row
#define FULLMASK 0xFFFFFFFFu

__device__ float g_w[(size_t)8 * NPIX];   // normalized fp32 weights, planar [8][B*H*W]
__device__ float g_ping[NPIX];            // scratch disparity buffers
__device__ float g_pong[NPIX];

// ---------------------------------------------------------------------------
// Fused pass: 8 stencil iterations, trapezoidal blocking (64x64 region ->
// 48x48 output). 1024 threads/CTA, 4 px/thread:
//   q = tid & 15 (quad), r = tid >> 4 (region row), lane = (r&1)*16 + q.
// Lateral halos via warp shuffle (lane+-1 = adjacent quad, same row); the
// only smem ops are 2x LDS.128 (top/bottom quad) + 1x STS.128 per iter.
// Shuffles that cross the halfwarp/row boundary (q=0 left, q=15 right) feed
// only acc[0]/acc[3], which the region-edge fixups discard.
// Update form: d' = d + sum_i w_i * (d_i - d).
// PREP: pass 1 normalizes kernel_raw in-register, stores g_w owned window.
// ---------------------------------------------------------------------------
template <bool PREP, bool CLIP>
__global__ void __launch_bounds__(1024) fused_kernel(const float* __restrict__ din,
                                                     float* __restrict__ dout,
                                                     const float* __restrict__ raw) {
    __shared__ float sbuf[2][RS * SROW];

    const int tid = threadIdx.x;
    const int q   = tid & 15;           // quad
    const int r   = tid >> 4;           // region row 0..63
    const int x0  = q << 2;             // region col of px0

    const int b   = blockIdx.z;
    const int gy  = blockIdx.y * TS - TT + r;
    const int gx0 = blockIdx.x * TS - TT + x0;
    const bool rowIn = (gy >= 0) && (gy < HH);
    const size_t rowOff = (size_t)(b * HH + gy) * WW;  // deref'd only when rowIn
    const bool pxIn  = rowIn && gx0 >= 0 && gx0 < WW;

    // ---- own disparity quad (zero outside image) ----
    float mm[6];                         // [halo-1, px0..3, halo+4]
    {
        float4 v = make_float4(0.f, 0.f, 0.f, 0.f);
        if (pxIn) v = *reinterpret_cast<const float4*>(din + rowOff + gx0);
        mm[1] = v.x; mm[2] = v.y; mm[3] = v.z; mm[4] = v.w;
    }

    // ---- per-pixel weights into registers (zero outside image) ----
    float w[8][4];                       // [channel][px]
#pragma unroll
    for (int ch = 0; ch < 8; ch++) {
        const float* base = PREP
            ? raw + (size_t)(b * 8 + ch) * PLANE
            : g_w + (size_t)ch * NPIX + (size_t)b * PLANE;
        float4 v = make_float4(0.f, 0.f, 0.f, 0.f);
        if (pxIn) v = *reinterpret_cast<const float4*>(base + (size_t)gy * WW + gx0);
        w[ch][0] = v.x; w[ch][1] = v.y; w[ch][2] = v.z; w[ch][3] = v.w;
    }

    if (PREP) {
#pragma unroll
        for (int p = 0; p < 4; p++) {
            float s = 0.f;
#pragma unroll
            for (int ch = 0; ch < 8; ch++) s += fabsf(w[ch][p]);
            float inv = __frcp_rn(s + 1e-9f);
#pragma unroll
            for (int ch = 0; ch < 8; ch++) w[ch][p] *= inv;
        }
        // store owned (non-overlapping) window: region cols [8,56), rows [8,56)
        if (q >= 2 && q <= 13 && r >= TT && r < RS - TT && gy < HH && gx0 < WW) {
#pragma unroll
            for (int ch = 0; ch < 8; ch++)
                *reinterpret_cast<float4*>(g_w + (size_t)ch * NPIX + rowOff + gx0) =
                    make_float4(w[ch][0], w[ch][1], w[ch][2], w[ch][3]);
        }
    }

    // ---- initial publish to buffer 0 ----
    *reinterpret_cast<float4*>(&sbuf[0][r * SROW + x0]) =
        make_float4(mm[1], mm[2], mm[3], mm[4]);
    __syncthreads();

    const bool act = (r >= 1) && (r <= RS - 2);
    const int  tr  = (r >= 1) ? r - 1 : 0;          // clamped (result unused when inactive)
    const int  br  = (r <= RS - 2) ? r + 1 : RS - 1;

    // ---- 8 fused iterations ----
#pragma unroll
    for (int it = 0; it < TT; it++) {
        const float* cur = sbuf[it & 1];

        // own-row lateral halos via shuffle (start-of-iter state)
        mm[0] = __shfl_up_sync(FULLMASK, mm[4], 1);
        mm[5] = __shfl_down_sync(FULLMASK, mm[1], 1);

        float t[6], acc[4];

        // top row: wide load + shuffled halos
        {
            float4 a = *reinterpret_cast<const float4*>(cur + tr * SROW + x0);
            t[1] = a.x; t[2] = a.y; t[3] = a.z; t[4] = a.w;
            t[0] = __shfl_up_sync(FULLMASK, a.w, 1);
            t[5] = __shfl_down_sync(FULLMASK, a.x, 1);
        }
#pragma unroll
        for (int p = 0; p < 4; p++) {
            float d = mm[p + 1];
            float a = d;
            a = fmaf(w[0][p], t[p]      - d, a);  // (y-1, x-1)
            a = fmaf(w[1][p], t[p + 1]  - d, a);  // (y-1, x  )
            a = fmaf(w[2][p], t[p + 2]  - d, a);  // (y-1, x+1)
            a = fmaf(w[3][p], mm[p + 2] - d, a);  // (y  , x+1)
            a = fmaf(w[7][p], mm[p]     - d, a);  // (y  , x-1)
            acc[p] = a;
        }

        // bottom row: wide load + shuffled halos (reuse t[])
        {
            float4 a = *reinterpret_cast<const float4*>(cur + br * SROW + x0);
            t[1] = a.x; t[2] = a.y; t[3] = a.z; t[4] = a.w;
            t[0] = __shfl_up_sync(FULLMASK, a.w, 1);
            t[5] = __shfl_down_sync(FULLMASK, a.x, 1);
        }
#pragma unroll
        for (int p = 0; p < 4; p++) {
            float d = mm[p + 1];
            acc[p] = fmaf(w[4][p], t[p + 2] - d, acc[p]);  // (y+1, x+1)
            acc[p] = fmaf(w[5][p], t[p + 1] - d, acc[p]);  // (y+1, x  )
            acc[p] = fmaf(w[6][p], t[p]     - d, acc[p]);  // (y+1, x-1)
        }

        // region-edge columns keep old value (consumed only while still valid;
        // also absorbs garbage shuffles at halfwarp boundaries)
        if (q == 0)  acc[0] = mm[1];
        if (q == 15) acc[3] = mm[4];

        if (act) {
            mm[1] = acc[0]; mm[2] = acc[1]; mm[3] = acc[2]; mm[4] = acc[3];
        }

        if (it < TT - 1) {
            *reinterpret_cast<float4*>(&sbuf[(it + 1) & 1][r * SROW + x0]) =
                make_float4(mm[1], mm[2], mm[3], mm[4]);
            __syncthreads();
        }
    }

    // ---- epilogue: write owned window (region cols [8,56), rows [8,56)) ----
    if (q >= 2 && q <= 13 && r >= TT && r < RS - TT && gy < HH && gx0 < WW) {
        if (CLIP) {
#pragma unroll
            for (int p = 0; p < 4; p++)
                mm[1 + p] = fminf(fmaxf(mm[1 + p], 0.f), 256.f);
        }
        *reinterpret_cast<float4*>(dout + rowOff + gx0) =
            make_float4(mm[1], mm[2], mm[3], mm[4]);
    }
}

// ---------------------------------------------------------------------------
extern "C" void kernel_launch(void* const* d_in, const int* in_sizes, int n_in,
                              void* d_out, int out_size) {
    const float* disp = (const float*)d_in[0];
    const float* raw  = (const float*)d_in[1];
    if (n_in >= 2 && in_sizes[0] > in_sizes[1]) {  // defensive order check
        const float* t = disp; disp = raw; raw = t;
    }
    float* out = (float*)d_out;

    float* ping = nullptr; float* pong = nullptr;
    cudaGetSymbolAddress((void**)&ping, g_ping);   // address queries; capture-safe
    cudaGetSymbolAddress((void**)&pong, g_pong);

    dim3 grid(NTX, NTY, BB);
    // 3 fused passes x 8 iterations = 24; pass 1 also normalizes weights
    fused_kernel<true,  false><<<grid, 1024>>>(disp, ping, raw);
    fused_kernel<false, false><<<grid, 1024>>>(ping, pong, raw);
    fused_kernel<false, true ><<<grid, 1024>>>(pong, out,  raw);
}

// round 14
// speedup vs baseline: 2.3454x; 1.0897x over previous
#include <cuda_runtime.h>

// Shape fixed by dataset: disp [4,1,1024,1280] f32, kernel_raw [4,8,1024,1280] f32
#define BB    4
#define HH    1024
#define WW    1280
#define PLANE (HH * WW)
#define NPIX  (BB * PLANE)     // 5242880

#define TT    8                // fused iterations per pass (24 = 3 passes)
#define TS    48               // output tile (quad-aligned: halo 8 = 2 quads)
#define RS    64               // region tile
#define NTX   ((WW + TS - 1) / TS)   // 27
#define NTY   ((HH + TS - 1) / TS)   // 22
#define SROW  64               // floats per smem row
#define FULLMASK 0xFFFFFFFFu

__device__ float g_w[(size_t)8 * NPIX];   // normalized fp32 weights, planar [8][B*H*W]
__device__ float g_ping[NPIX];            // scratch disparity buffers
__device__ float g_pong[NPIX];

// ---------------------------------------------------------------------------
// Fused pass: 8 stencil iterations, trapezoidal blocking (64x64 region ->
// 48x48 output). 1024 threads/CTA, 4 px/thread:
//   q = tid & 15 (quad), r = tid >> 4 (region row), lane = (r&1)*16 + q.
// Lateral halos via warp shuffle; smem ops per iter: 2x LDS.128 + 1x STS.128.
// DIRECT update form: d' = w0*d + sum_i w_i*d_i with w0 = 1 - sum w
// (9 math ops/px-iter vs 16 for the diff form; exact round-2 numerics).
// Out-of-image px: w==0 -> w0=1 -> stays 0, reproducing zero padding.
// PREP: pass 1 normalizes kernel_raw in-register, stores g_w owned window.
// ---------------------------------------------------------------------------
template <bool PREP, bool CLIP>
__global__ void __launch_bounds__(1024) fused_kernel(const float* __restrict__ din,
                                                     float* __restrict__ dout,
                                                     const float* __restrict__ raw) {
    __shared__ float sbuf[2][RS * SROW];

    const int tid = threadIdx.x;
    const int q   = tid & 15;           // quad
    const int r   = tid >> 4;           // region row 0..63
    const int x0  = q << 2;             // region col of px0

    const int b   = blockIdx.z;
    const int gy  = blockIdx.y * TS - TT + r;
    const int gx0 = blockIdx.x * TS - TT + x0;
    const bool rowIn = (gy >= 0) && (gy < HH);
    const size_t rowOff = (size_t)(b * HH + gy) * WW;  // deref'd only when rowIn
    const bool pxIn  = rowIn && gx0 >= 0 && gx0 < WW;

    // ---- own disparity quad (zero outside image) ----
    float mm[6];                         // [halo-1, px0..3, halo+4]
    {
        float4 v = make_float4(0.f, 0.f, 0.f, 0.f);
        if (pxIn) v = *reinterpret_cast<const float4*>(din + rowOff + gx0);
        mm[1] = v.x; mm[2] = v.y; mm[3] = v.z; mm[4] = v.w;
    }

    // ---- per-pixel weights into registers (zero outside image) ----
    float w[8][4];                       // [channel][px]
#pragma unroll
    for (int ch = 0; ch < 8; ch++) {
        const float* base = PREP
            ? raw + (size_t)(b * 8 + ch) * PLANE
            : g_w + (size_t)ch * NPIX + (size_t)b * PLANE;
        float4 v = make_float4(0.f, 0.f, 0.f, 0.f);
        if (pxIn) v = *reinterpret_cast<const float4*>(base + (size_t)gy * WW + gx0);
        w[ch][0] = v.x; w[ch][1] = v.y; w[ch][2] = v.z; w[ch][3] = v.w;
    }

    if (PREP) {
#pragma unroll
        for (int p = 0; p < 4; p++) {
            float s = 0.f;
#pragma unroll
            for (int ch = 0; ch < 8; ch++) s += fabsf(w[ch][p]);
            float inv = __frcp_rn(s + 1e-9f);
#pragma unroll
            for (int ch = 0; ch < 8; ch++) w[ch][p] *= inv;
        }
        // store owned (non-overlapping) window: region cols [8,56), rows [8,56)
        if (q >= 2 && q <= 13 && r >= TT && r < RS - TT && gy < HH && gx0 < WW) {
#pragma unroll
            for (int ch = 0; ch < 8; ch++)
                *reinterpret_cast<float4*>(g_w + (size_t)ch * NPIX + rowOff + gx0) =
                    make_float4(w[ch][0], w[ch][1], w[ch][2], w[ch][3]);
        }
    }

    // center weight w0 = 1 - sum(w)
    float w0[4];
#pragma unroll
    for (int p = 0; p < 4; p++) {
        float s = ((w[0][p] + w[1][p]) + (w[2][p] + w[3][p])) +
                  ((w[4][p] + w[5][p]) + (w[6][p] + w[7][p]));
        w0[p] = 1.0f - s;
    }

    // ---- initial publish to buffer 0 ----
    *reinterpret_cast<float4*>(&sbuf[0][r * SROW + x0]) =
        make_float4(mm[1], mm[2], mm[3], mm[4]);
    __syncthreads();

    const bool act = (r >= 1) && (r <= RS - 2);
    // precomputed offsets (clamped rows: result unused when inactive)
    const int trOff = ((r >= 1) ? r - 1 : 0) * SROW + x0;
    const int brOff = ((r <= RS - 2) ? r + 1 : RS - 1) * SROW + x0;
    const int mrOff = r * SROW + x0;

    // ---- 8 fused iterations ----
#pragma unroll
    for (int it = 0; it < TT; it++) {
        const float* cur = sbuf[it & 1];

        // own-row lateral halos via shuffle (start-of-iter state)
        mm[0] = __shfl_up_sync(FULLMASK, mm[4], 1);
        mm[5] = __shfl_down_sync(FULLMASK, mm[1], 1);

        float t[6], acc[4];

        // top row: wide load + shuffled halos
        {
            float4 a = *reinterpret_cast<const float4*>(cur + trOff);
            t[1] = a.x; t[2] = a.y; t[3] = a.z; t[4] = a.w;
            t[0] = __shfl_up_sync(FULLMASK, a.w, 1);
            t[5] = __shfl_down_sync(FULLMASK, a.x, 1);
        }
#pragma unroll
        for (int p = 0; p < 4; p++) {
            float a = w0[p] * mm[p + 1];
            a = fmaf(w[0][p], t[p],      a);  // (y-1, x-1)
            a = fmaf(w[1][p], t[p + 1],  a);  // (y-1, x  )
            a = fmaf(w[2][p], t[p + 2],  a);  // (y-1, x+1)
            a = fmaf(w[3][p], mm[p + 2], a);  // (y  , x+1)
            a = fmaf(w[7][p], mm[p],     a);  // (y  , x-1)
            acc[p] = a;
        }

        // bottom row: wide load + shuffled halos (reuse t[])
        {
            float4 a = *reinterpret_cast<const float4*>(cur + brOff);
            t[1] = a.x; t[2] = a.y; t[3] = a.z; t[4] = a.w;
            t[0] = __shfl_up_sync(FULLMASK, a.w, 1);
            t[5] = __shfl_down_sync(FULLMASK, a.x, 1);
        }
#pragma unroll
        for (int p = 0; p < 4; p++) {
            acc[p] = fmaf(w[4][p], t[p + 2], acc[p]);  // (y+1, x+1)
            acc[p] = fmaf(w[5][p], t[p + 1], acc[p]);  // (y+1, x  )
            acc[p] = fmaf(w[6][p], t[p],     acc[p]);  // (y+1, x-1)
        }

        // region-edge columns keep old value (consumed only while still valid;
        // also absorbs garbage shuffles at halfwarp boundaries)
        if (q == 0)  acc[0] = mm[1];
        if (q == 15) acc[3] = mm[4];

        if (act) {
            mm[1] = acc[0]; mm[2] = acc[1]; mm[3] = acc[2]; mm[4] = acc[3];
        }

        if (it < TT - 1) {
            *reinterpret_cast<float4*>(&sbuf[(it + 1) & 1][mrOff]) =
                make_float4(mm[1], mm[2], mm[3], mm[4]);
            __syncthreads();
        }
    }

    // ---- epilogue: write owned window (region cols [8,56), rows [8,56)) ----
    if (q >= 2 && q <= 13 && r >= TT && r < RS - TT && gy < HH && gx0 < WW) {
        if (CLIP) {
#pragma unroll
            for (int p = 0; p < 4; p++)
                mm[1 + p] = fminf(fmaxf(mm[1 + p], 0.f), 256.f);
        }
        *reinterpret_cast<float4*>(dout + rowOff + gx0) =
            make_float4(mm[1], mm[2], mm[3], mm[4]);
    }
}

// ---------------------------------------------------------------------------
extern "C" void kernel_launch(void* const* d_in, const int* in_sizes, int n_in,
                              void* d_out, int out_size) {
    const float* disp = (const float*)d_in[0];
    const float* raw  = (const float*)d_in[1];
    if (n_in >= 2 && in_sizes[0] > in_sizes[1]) {  // defensive order check
        const float* t = disp; disp = raw; raw = t;
    }
    float* out = (float*)d_out;

    float* ping = nullptr; float* pong = nullptr;
    cudaGetSymbolAddress((void**)&ping, g_ping);   // address queries; capture-safe
    cudaGetSymbolAddress((void**)&pong, g_pong);

    dim3 grid(NTX, NTY, BB);
    // 3 fused passes x 8 iterations = 24; pass 1 also normalizes weights
    fused_kernel<true,  false><<<grid, 1024>>>(disp, ping, raw);
    fused_kernel<false, false><<<grid, 1024>>>(ping, pong, raw);
    fused_kernel<false, true ><<<grid, 1024>>>(pong, out,  raw);
}